// round 11
// baseline (speedup 1.0000x reference)
#include <cuda_runtime.h>
#include <cstdint>

// Problem constants
#define TT   8
#define NN   100000
#define DD   128
#define EE   50000
#define HH0  64
#define HH1  32

// cos pipeline config: one t per item, 2 rows (1KB) per stage, DEEP pipeline
#define CWARPS 4          // warps per block
#define SLOTS  8          // smem slots per warp
#define PD     7          // prefetch distance (cp.async groups in flight)
#define STAGE_FLOATS 256  // 2 rows x 128 floats
#define STAGE_BYTES  1024
#define TOTAL_ITEMS  (TT * EE)   // 400k items, t-major

// mlp config: one wave, 2 edges per thread (R9, kept unchanged)
#define MLP_BLOCKS 98
#define MLP_NT     (MLP_BLOCKS * 256)

__device__ float g_sim[EE * TT];   // s1 stored [e][t] for coalesced MLP reads

// Packed f32x2 helpers (Blackwell FFMA2 path — PTX only)
__device__ __forceinline__ unsigned long long mul2(unsigned long long a, unsigned long long b) {
    unsigned long long r;
    asm("mul.rn.f32x2 %0, %1, %2;" : "=l"(r) : "l"(a), "l"(b));
    return r;
}
__device__ __forceinline__ unsigned long long fma2(unsigned long long a, unsigned long long b, unsigned long long c) {
    unsigned long long r;
    asm("fma.rn.f32x2 %0, %1, %2, %3;" : "=l"(r) : "l"(a), "l"(b), "l"(c));
    return r;
}
__device__ __forceinline__ float hsum2(unsigned long long v) {
    float a, b;
    asm("mov.b64 {%0, %1}, %2;" : "=f"(a), "=f"(b) : "l"(v));
    return a + b;
}
__device__ __forceinline__ unsigned long long pack2(float lo, float hi) {
    unsigned long long r;
    asm("mov.b64 %0, {%1, %2};" : "=l"(r) : "f"(lo), "f"(hi));
    return r;
}

// 16B-chunk swizzle within a 512B row (q in 0..31): position = q ^ (q>>3).
__device__ __forceinline__ unsigned swz16(unsigned q) { return q ^ (q >> 3); }

// ---------------------------------------------------------------------------
// Cosine kernel, cp.async pipeline, ONE t per item (t-major), PD=7.
// Item j -> t = j/EE, e = j%EE. Each stage = 2 gathered rows (src,dst) = 1KB.
// Deep prefetch (7 groups in flight per warp) divides the loaded-DRAM latency
// by 7 instead of 3 — the R7/R10 data showed iteration time was set by
// latency/PD (issue pinned at ~24% in both), so this is the binding knob.
// ---------------------------------------------------------------------------
__global__ void __launch_bounds__(CWARPS * 32) cos_kernel(const void* __restrict__ el,
                                                          const float* __restrict__ z1,
                                                          const float* __restrict__ w1) {
    __shared__ float sbuf[CWARPS][SLOTS][STAGE_FLOATS];

    const int lane = threadIdx.x & 31;
    const int wid  = threadIdx.x >> 5;
    const int m    = lane >> 3;     // head index 0..3
    const int dg   = lane & 7;      // d-chunk 0..7 (16 floats each)
    const int gw   = (int)((blockIdx.x * blockDim.x + threadIdx.x) >> 5);
    const int nw   = (int)((gridDim.x * blockDim.x) >> 5);
    const int TOTAL = TOTAL_ITEMS;

    // Inline int64-vs-int32 edge dtype detection (warp-uniform)
    const int* ew = (const int*)el;
    int is64 = 1;
#pragma unroll
    for (int i = 1; i < 16; i += 2) is64 &= (ew[i] == 0);

    // Hoist w^2 for this lane's (m, d-chunk): 8 packed f32x2 values
    unsigned long long w2p[8];
    {
        const ulonglong2* wp = (const ulonglong2*)(w1 + m * DD + dg * 16);
#pragma unroll
        for (int i = 0; i < 4; i++) {
            ulonglong2 w = __ldg(wp + i);
            w2p[2 * i]     = mul2(w.x, w.x);
            w2p[2 * i + 1] = mul2(w.y, w.y);
        }
    }

    // Read offsets: global 16B chunk (dg*4+c) lives at smem position swz16(.)
    unsigned roff[4];
#pragma unroll
    for (int c = 0; c < 4; c++) roff[c] = swz16((unsigned)dg * 4 + c) * 16;

    // cp.async: lane copies GLOBAL chunk `lane` (of a 512B row) into smem
    // position swz16(lane). Source unswizzled, destination swizzled.
    const unsigned goff = (unsigned)lane * 16;
    const unsigned woff = swz16((unsigned)lane) * 16;

    const unsigned sbase = (unsigned)__cvta_generic_to_shared(&sbuf[wid][0][0]);

    // --- helpers -----------------------------------------------------------
    auto loadEdge = [&](int j) -> int2 {
        int jc = j < TOTAL ? j : TOTAL - 1;
        int e  = jc % EE;
        int2 r;
        if (is64) {
            longlong2 v = __ldg((const longlong2*)el + e);
            r.x = (int)v.x; r.y = (int)v.y;
        } else {
            r = __ldg((const int2*)el + e);
        }
        return r;
    };

    auto prefetch = [&](int j, int2 ed, int slot) {
        if (j < TOTAL) {
            int tp = j / EE;
            const char* zA = (const char*)z1 + (size_t)tp * NN * 512;
            const char* g0 = zA + (size_t)(unsigned)ed.x * 512 + goff;
            const char* g1 = zA + (size_t)(unsigned)ed.y * 512 + goff;
            unsigned sm = sbase + (unsigned)slot * STAGE_BYTES + woff;
            asm volatile("cp.async.cg.shared.global [%0], [%1], 16;\n" :: "r"(sm),       "l"(g0));
            asm volatile("cp.async.cg.shared.global [%0], [%1], 16;\n" :: "r"(sm + 512), "l"(g1));
        }
        asm volatile("cp.async.commit_group;\n");  // empty group OK when guarded out
    };
    // ------------------------------------------------------------------------

    // Prologue: PD=7 groups in flight + edge register ring 2 iterations deep
#pragma unroll
    for (int p = 0; p < PD; p++)
        prefetch(gw + p * nw, loadEdge(gw + p * nw), p);
    int2 ering[2];
    ering[0] = loadEdge(gw + PD * nw);           // consumed at cnt=0 -> j+7nw
    ering[1] = loadEdge(gw + (PD + 1) * nw);     // consumed at cnt=1

    int cnt = 0;
#pragma unroll 1
    for (int j = gw; j < TOTAL; j += nw, cnt++) {
        asm volatile("cp.async.wait_group %0;\n" :: "n"(PD - 1));
        __syncwarp();

        const int slot = cnt & (SLOTS - 1);
        const char* st = (const char*)&sbuf[wid][slot][0];

        // ---- compute from smem ----
        unsigned long long d0 = 0ull, na0 = 0ull, nb0 = 0ull;
#pragma unroll
        for (int c = 0; c < 4; c++) {
            ulonglong2 a0 = *(const ulonglong2*)(st +       roff[c]);
            ulonglong2 b0 = *(const ulonglong2*)(st + 512 + roff[c]);

            d0  = fma2(mul2(a0.x, b0.x), w2p[2 * c],     d0);
            na0 = fma2(mul2(a0.x, a0.x), w2p[2 * c],     na0);
            nb0 = fma2(mul2(b0.x, b0.x), w2p[2 * c],     nb0);
            d0  = fma2(mul2(a0.y, b0.y), w2p[2 * c + 1], d0);
            na0 = fma2(mul2(a0.y, a0.y), w2p[2 * c + 1], na0);
            nb0 = fma2(mul2(b0.y, b0.y), w2p[2 * c + 1], nb0);
        }

        // Prefetch next stage NOW so LDGSTS issue overlaps the reduction tail.
        // Edge consumed here was loaded 2 iterations ago (ring depth 2).
        prefetch(j + PD * nw, ering[cnt & 1], (cnt + PD) & (SLOTS - 1));
        ering[cnt & 1] = loadEdge(j + (PD + 2) * nw);

        float dot = hsum2(d0), sa = hsum2(na0), sb = hsum2(nb0);

#pragma unroll
        for (int ofs = 1; ofs <= 4; ofs <<= 1) {
            dot += __shfl_xor_sync(0xffffffffu, dot, ofs);
            sa  += __shfl_xor_sync(0xffffffffu, sa,  ofs);
            sb  += __shfl_xor_sync(0xffffffffu, sb,  ofs);
        }

        // max(sqrt(x), 1e-8) == sqrt(max(x, 1e-16)) for x >= 0
        float c = dot * rsqrtf(fmaxf(sa, 1e-16f) * fmaxf(sb, 1e-16f));

        // Mean over 4 heads (sum across quarters)
        c += __shfl_xor_sync(0xffffffffu, c, 8);
        c += __shfl_xor_sync(0xffffffffu, c, 16);

        if (lane == 0) {
            int tp = j / EE;
            int e  = j - tp * EE;
            g_sim[e * TT + tp] = 0.25f * c;
        }
    }
}

// ---------------------------------------------------------------------------
// MLP kernel (R9/R10, kept unchanged): TWO edges per thread, one wave.
// ---------------------------------------------------------------------------
__global__ void __launch_bounds__(256) mlp_kernel(const float* __restrict__ W0,
                                                  const float* __restrict__ b0,
                                                  const float* __restrict__ W1,
                                                  const float* __restrict__ b1,
                                                  const float* __restrict__ Wp,
                                                  const float* __restrict__ bp,
                                                  float* __restrict__ out) {
    __shared__ float sW0[HH0 * TT];        // 512
    __shared__ float sb0[HH0];
    __shared__ float sW1t[HH0 * HH1];      // transposed: [j][k]
    __shared__ float sb1[HH1];
    __shared__ float sWp[HH1];
    __shared__ float sbp;

    const int tid = threadIdx.x;
    for (int i = tid; i < HH0 * TT; i += 256) sW0[i] = W0[i];
    for (int i = tid; i < HH1 * HH0; i += 256) {
        int k = i / HH0, j = i - k * HH0;          // W1 is [k][j]
        sW1t[j * HH1 + k] = W1[i];
    }
    if (tid < HH0) sb0[tid] = b0[tid];
    if (tid < HH1) { sb1[tid] = b1[tid]; sWp[tid] = Wp[tid]; }
    if (tid == 0) sbp = bp[0];
    __syncthreads();

    const int e0 = blockIdx.x * 256 + tid;
    const int e1 = e0 + MLP_NT;
    const bool v1 = (e1 < EE);
    const int e1c = v1 ? e1 : (EE - 1);

    ulonglong2 sva0 = *(const ulonglong2*)(g_sim + e0  * 8);
    ulonglong2 sva1 = *(const ulonglong2*)(g_sim + e0  * 8 + 4);
    ulonglong2 svb0 = *(const ulonglong2*)(g_sim + e1c * 8);
    ulonglong2 svb1 = *(const ulonglong2*)(g_sim + e1c * 8 + 4);

    unsigned long long accA[HH1 / 2], accB[HH1 / 2];
#pragma unroll
    for (int k = 0; k < HH1 / 2; k++) {
        unsigned long long b = ((const unsigned long long*)sb1)[k];
        accA[k] = b; accB[k] = b;
    }

#pragma unroll
    for (int j = 0; j < HH0; j++) {
        const ulonglong2* w = (const ulonglong2*)(sW0 + j * TT);
        ulonglong2 w0 = w[0], w1v = w[1];

        unsigned long long tA = mul2(sva0.x, w0.x);
        unsigned long long tB = mul2(svb0.x, w0.x);
        tA = fma2(sva0.y, w0.y, tA);
        tB = fma2(svb0.y, w0.y, tB);
        tA = fma2(sva1.x, w1v.x, tA);
        tB = fma2(svb1.x, w1v.x, tB);
        tA = fma2(sva1.y, w1v.y, tA);
        tB = fma2(svb1.y, w1v.y, tB);
        float hA = fmaxf(hsum2(tA) + sb0[j], 0.0f);
        float hB = fmaxf(hsum2(tB) + sb0[j], 0.0f);
        unsigned long long hA2 = pack2(hA, hA);
        unsigned long long hB2 = pack2(hB, hB);

        const ulonglong2* wr = (const ulonglong2*)(sW1t + j * HH1);
#pragma unroll
        for (int k2 = 0; k2 < HH1 / 4; k2++) {
            ulonglong2 wv = wr[k2];
            accA[2 * k2]     = fma2(hA2, wv.x, accA[2 * k2]);
            accA[2 * k2 + 1] = fma2(hA2, wv.y, accA[2 * k2 + 1]);
            accB[2 * k2]     = fma2(hB2, wv.x, accB[2 * k2]);
            accB[2 * k2 + 1] = fma2(hB2, wv.y, accB[2 * k2 + 1]);
        }
    }

    float predA = sbp, predB = sbp;
#pragma unroll
    for (int k = 0; k < HH1 / 2; k++) {
        float xA, yA, xB, yB;
        asm("mov.b64 {%0, %1}, %2;" : "=f"(xA), "=f"(yA) : "l"(accA[k]));
        asm("mov.b64 {%0, %1}, %2;" : "=f"(xB), "=f"(yB) : "l"(accB[k]));
        predA += fmaxf(xA, 0.0f) * sWp[2 * k] + fmaxf(yA, 0.0f) * sWp[2 * k + 1];
        predB += fmaxf(xB, 0.0f) * sWp[2 * k] + fmaxf(yB, 0.0f) * sWp[2 * k + 1];
    }
    out[e0] = predA;
    if (v1) out[e1] = predB;
}

// ---------------------------------------------------------------------------
// Launch. Input order (metadata): edge_list, z1_trains, z2_trains(unused),
// weight_vec1, weight_vec2(unused), W0, b0, W1, b1, Wp, bp
// ---------------------------------------------------------------------------
extern "C" void kernel_launch(void* const* d_in, const int* in_sizes, int n_in,
                              void* d_out, int out_size) {
    const void*  edge = d_in[0];
    const float* z1   = (const float*)d_in[1];
    const float* w1   = (const float*)d_in[3];
    const float* W0   = (const float*)d_in[5];
    const float* b0   = (const float*)d_in[6];
    const float* W1   = (const float*)d_in[7];
    const float* b1   = (const float*)d_in[8];
    const float* Wp   = (const float*)d_in[9];
    const float* bp   = (const float*)d_in[10];

    cos_kernel<<<888, CWARPS * 32>>>(edge, z1, w1);
    mlp_kernel<<<MLP_BLOCKS, 256>>>(W0, b0, W1, b1, Wp, bp, (float*)d_out);
}

// round 12
// speedup vs baseline: 1.1199x; 1.1199x over previous
#include <cuda_runtime.h>
#include <cstdint>

// Problem constants
#define TT   8
#define NN   100000
#define DD   128
#define EE   50000
#define HH0  64
#define HH1  32

// cos pipeline config (R7 proven): t-pair items, 4 rows (2KB) per stage
#define CWARPS 4          // warps per block
#define SLOTS  4          // smem slots per warp
#define PD     3          // prefetch distance (cp.async groups in flight)
#define STAGE_FLOATS 512  // 4 rows x 128 floats
#define STAGE_BYTES  2048
#define TOTAL_ITEMS  (4 * EE)    // 200k t-pair items: tp in 0..3

// mlp config: one wave, 2 edges per thread (R9, kept unchanged)
#define MLP_BLOCKS 98
#define MLP_NT     (MLP_BLOCKS * 256)

__device__ float g_sim[EE * TT];   // s1 stored [e][t] for coalesced MLP reads

// Packed f32x2 helpers (Blackwell FFMA2 path — PTX only)
__device__ __forceinline__ unsigned long long mul2(unsigned long long a, unsigned long long b) {
    unsigned long long r;
    asm("mul.rn.f32x2 %0, %1, %2;" : "=l"(r) : "l"(a), "l"(b));
    return r;
}
__device__ __forceinline__ unsigned long long fma2(unsigned long long a, unsigned long long b, unsigned long long c) {
    unsigned long long r;
    asm("fma.rn.f32x2 %0, %1, %2, %3;" : "=l"(r) : "l"(a), "l"(b), "l"(c));
    return r;
}
__device__ __forceinline__ float hsum2(unsigned long long v) {
    float a, b;
    asm("mov.b64 {%0, %1}, %2;" : "=f"(a), "=f"(b) : "l"(v));
    return a + b;
}
__device__ __forceinline__ unsigned long long pack2(float lo, float hi) {
    unsigned long long r;
    asm("mov.b64 %0, {%1, %2};" : "=l"(r) : "f"(lo), "f"(hi));
    return r;
}

// 16B-chunk swizzle within a 512B row (q in 0..31): position = q ^ (q>>3).
__device__ __forceinline__ unsigned swz16(unsigned q) { return q ^ (q >> 3); }

// ---------------------------------------------------------------------------
// Cosine kernel (R7 structure), processing t-pair items j in [jbeg, jend).
// Item j -> tp = j/EE in 0..3, e = j%EE; handles times (tp, tp+4) with one
// edge fetch. Stage = 4 gathered rows (a0,b0,a1,b1) = 2KB; SLOTS=4, PD=3.
// This exact structure measured 83.5 us for all 200k items — best known.
// ---------------------------------------------------------------------------
__global__ void __launch_bounds__(CWARPS * 32) cos_kernel(const void* __restrict__ el,
                                                          const float* __restrict__ z1,
                                                          const float* __restrict__ w1,
                                                          int jbeg, int jend) {
    __shared__ float sbuf[CWARPS][SLOTS][STAGE_FLOATS];

    const int lane = threadIdx.x & 31;
    const int wid  = threadIdx.x >> 5;
    const int m    = lane >> 3;     // head index 0..3
    const int dg   = lane & 7;      // d-chunk 0..7 (16 floats each)
    const int gw   = (int)((blockIdx.x * blockDim.x + threadIdx.x) >> 5);
    const int nw   = (int)((gridDim.x * blockDim.x) >> 5);

    // Inline int64-vs-int32 edge dtype detection (warp-uniform)
    const int* ew = (const int*)el;
    int is64 = 1;
#pragma unroll
    for (int i = 1; i < 16; i += 2) is64 &= (ew[i] == 0);

    // Hoist w^2 for this lane's (m, d-chunk): 8 packed f32x2 values
    unsigned long long w2p[8];
    {
        const ulonglong2* wp = (const ulonglong2*)(w1 + m * DD + dg * 16);
#pragma unroll
        for (int i = 0; i < 4; i++) {
            ulonglong2 w = __ldg(wp + i);
            w2p[2 * i]     = mul2(w.x, w.x);
            w2p[2 * i + 1] = mul2(w.y, w.y);
        }
    }

    // Read offsets: global 16B chunk (dg*4+c) lives at smem position swz16(.)
    unsigned roff[4];
#pragma unroll
    for (int c = 0; c < 4; c++) roff[c] = swz16((unsigned)dg * 4 + c) * 16;

    // cp.async: lane copies GLOBAL chunk `lane` into smem position swz16(lane)
    const unsigned goff = (unsigned)lane * 16;
    const unsigned woff = swz16((unsigned)lane) * 16;

    const unsigned sbase = (unsigned)__cvta_generic_to_shared(&sbuf[wid][0][0]);

    // --- helpers -----------------------------------------------------------
    auto loadEdge = [&](int j) -> int2 {
        int jc = j < jend ? j : jend - 1;
        int e  = jc % EE;
        int2 r;
        if (is64) {
            longlong2 v = __ldg((const longlong2*)el + e);
            r.x = (int)v.x; r.y = (int)v.y;
        } else {
            r = __ldg((const int2*)el + e);
        }
        return r;
    };

    auto prefetch = [&](int j, int2 ed, int slot) {
        if (j < jend) {
            int tp = j / EE;
            const char* zA = (const char*)z1 + (size_t)tp * NN * 512;
            const char* zB = zA + (size_t)4 * NN * 512;
            const char* g0 = zA + (size_t)(unsigned)ed.x * 512 + goff;
            const char* g1 = zA + (size_t)(unsigned)ed.y * 512 + goff;
            const char* g2 = zB + (size_t)(unsigned)ed.x * 512 + goff;
            const char* g3 = zB + (size_t)(unsigned)ed.y * 512 + goff;
            unsigned sm = sbase + (unsigned)slot * STAGE_BYTES + woff;
            asm volatile("cp.async.cg.shared.global [%0], [%1], 16;\n" :: "r"(sm),        "l"(g0));
            asm volatile("cp.async.cg.shared.global [%0], [%1], 16;\n" :: "r"(sm + 512),  "l"(g1));
            asm volatile("cp.async.cg.shared.global [%0], [%1], 16;\n" :: "r"(sm + 1024), "l"(g2));
            asm volatile("cp.async.cg.shared.global [%0], [%1], 16;\n" :: "r"(sm + 1536), "l"(g3));
        }
        asm volatile("cp.async.commit_group;\n");  // empty group OK when guarded out
    };
    // ------------------------------------------------------------------------

    const int j0 = jbeg + gw;
    // Prologue: PD groups in flight + edge register ring 2 iterations deep
    prefetch(j0,          loadEdge(j0),          0);
    prefetch(j0 + nw,     loadEdge(j0 + nw),     1);
    prefetch(j0 + 2 * nw, loadEdge(j0 + 2 * nw), 2);
    int2 ering[2];
    ering[0] = loadEdge(j0 + 3 * nw);
    ering[1] = loadEdge(j0 + 4 * nw);

    int cnt = 0;
#pragma unroll 1
    for (int j = j0; j < jend; j += nw, cnt++) {
        asm volatile("cp.async.wait_group %0;\n" :: "n"(PD - 1));
        __syncwarp();

        const int slot = cnt & (SLOTS - 1);
        const char* st = (const char*)&sbuf[wid][slot][0];

        // ---- compute both pairs from smem ----
        unsigned long long d0 = 0ull, na0 = 0ull, nb0 = 0ull;
        unsigned long long d1 = 0ull, na1 = 0ull, nb1 = 0ull;
#pragma unroll
        for (int c = 0; c < 4; c++) {
            ulonglong2 a0 = *(const ulonglong2*)(st +        roff[c]);
            ulonglong2 b0 = *(const ulonglong2*)(st + 512  + roff[c]);
            ulonglong2 a1 = *(const ulonglong2*)(st + 1024 + roff[c]);
            ulonglong2 b1 = *(const ulonglong2*)(st + 1536 + roff[c]);

            d0  = fma2(mul2(a0.x, b0.x), w2p[2 * c],     d0);
            na0 = fma2(mul2(a0.x, a0.x), w2p[2 * c],     na0);
            nb0 = fma2(mul2(b0.x, b0.x), w2p[2 * c],     nb0);
            d0  = fma2(mul2(a0.y, b0.y), w2p[2 * c + 1], d0);
            na0 = fma2(mul2(a0.y, a0.y), w2p[2 * c + 1], na0);
            nb0 = fma2(mul2(b0.y, b0.y), w2p[2 * c + 1], nb0);

            d1  = fma2(mul2(a1.x, b1.x), w2p[2 * c],     d1);
            na1 = fma2(mul2(a1.x, a1.x), w2p[2 * c],     na1);
            nb1 = fma2(mul2(b1.x, b1.x), w2p[2 * c],     nb1);
            d1  = fma2(mul2(a1.y, b1.y), w2p[2 * c + 1], d1);
            na1 = fma2(mul2(a1.y, a1.y), w2p[2 * c + 1], na1);
            nb1 = fma2(mul2(b1.y, b1.y), w2p[2 * c + 1], nb1);
        }

        // Prefetch next stage NOW so LDGSTS issue overlaps the reduction tail
        prefetch(j + PD * nw, ering[cnt & 1], (cnt + PD) & (SLOTS - 1));
        ering[cnt & 1] = loadEdge(j + 5 * nw);

        float dot0 = hsum2(d0), sa0 = hsum2(na0), sb0 = hsum2(nb0);
        float dot1 = hsum2(d1), sa1 = hsum2(na1), sb1 = hsum2(nb1);

#pragma unroll
        for (int ofs = 1; ofs <= 4; ofs <<= 1) {
            dot0 += __shfl_xor_sync(0xffffffffu, dot0, ofs);
            dot1 += __shfl_xor_sync(0xffffffffu, dot1, ofs);
            sa0  += __shfl_xor_sync(0xffffffffu, sa0,  ofs);
            sa1  += __shfl_xor_sync(0xffffffffu, sa1,  ofs);
            sb0  += __shfl_xor_sync(0xffffffffu, sb0,  ofs);
            sb1  += __shfl_xor_sync(0xffffffffu, sb1,  ofs);
        }

        // max(sqrt(x), 1e-8) == sqrt(max(x, 1e-16)) for x >= 0
        float c0 = dot0 * rsqrtf(fmaxf(sa0, 1e-16f) * fmaxf(sb0, 1e-16f));
        float c1 = dot1 * rsqrtf(fmaxf(sa1, 1e-16f) * fmaxf(sb1, 1e-16f));

        c0 += __shfl_xor_sync(0xffffffffu, c0, 8);
        c1 += __shfl_xor_sync(0xffffffffu, c1, 8);
        c0 += __shfl_xor_sync(0xffffffffu, c0, 16);
        c1 += __shfl_xor_sync(0xffffffffu, c1, 16);

        if (lane == 0) {
            int tp = j / EE;
            int e  = j - tp * EE;
            g_sim[e * TT + tp]     = 0.25f * c0;
            g_sim[e * TT + tp + 4] = 0.25f * c1;
        }
    }
}

// ---------------------------------------------------------------------------
// MLP kernel (R9/R10/R11, kept unchanged): TWO edges per thread, one wave.
// ---------------------------------------------------------------------------
__global__ void __launch_bounds__(256) mlp_kernel(const float* __restrict__ W0,
                                                  const float* __restrict__ b0,
                                                  const float* __restrict__ W1,
                                                  const float* __restrict__ b1,
                                                  const float* __restrict__ Wp,
                                                  const float* __restrict__ bp,
                                                  float* __restrict__ out) {
    __shared__ float sW0[HH0 * TT];        // 512
    __shared__ float sb0[HH0];
    __shared__ float sW1t[HH0 * HH1];      // transposed: [j][k]
    __shared__ float sb1[HH1];
    __shared__ float sWp[HH1];
    __shared__ float sbp;

    const int tid = threadIdx.x;
    for (int i = tid; i < HH0 * TT; i += 256) sW0[i] = W0[i];
    for (int i = tid; i < HH1 * HH0; i += 256) {
        int k = i / HH0, j = i - k * HH0;          // W1 is [k][j]
        sW1t[j * HH1 + k] = W1[i];
    }
    if (tid < HH0) sb0[tid] = b0[tid];
    if (tid < HH1) { sb1[tid] = b1[tid]; sWp[tid] = Wp[tid]; }
    if (tid == 0) sbp = bp[0];
    __syncthreads();

    const int e0 = blockIdx.x * 256 + tid;
    const int e1 = e0 + MLP_NT;
    const bool v1 = (e1 < EE);
    const int e1c = v1 ? e1 : (EE - 1);

    ulonglong2 sva0 = *(const ulonglong2*)(g_sim + e0  * 8);
    ulonglong2 sva1 = *(const ulonglong2*)(g_sim + e0  * 8 + 4);
    ulonglong2 svb0 = *(const ulonglong2*)(g_sim + e1c * 8);
    ulonglong2 svb1 = *(const ulonglong2*)(g_sim + e1c * 8 + 4);

    unsigned long long accA[HH1 / 2], accB[HH1 / 2];
#pragma unroll
    for (int k = 0; k < HH1 / 2; k++) {
        unsigned long long b = ((const unsigned long long*)sb1)[k];
        accA[k] = b; accB[k] = b;
    }

#pragma unroll
    for (int j = 0; j < HH0; j++) {
        const ulonglong2* w = (const ulonglong2*)(sW0 + j * TT);
        ulonglong2 w0 = w[0], w1v = w[1];

        unsigned long long tA = mul2(sva0.x, w0.x);
        unsigned long long tB = mul2(svb0.x, w0.x);
        tA = fma2(sva0.y, w0.y, tA);
        tB = fma2(svb0.y, w0.y, tB);
        tA = fma2(sva1.x, w1v.x, tA);
        tB = fma2(svb1.x, w1v.x, tB);
        tA = fma2(sva1.y, w1v.y, tA);
        tB = fma2(svb1.y, w1v.y, tB);
        float hA = fmaxf(hsum2(tA) + sb0[j], 0.0f);
        float hB = fmaxf(hsum2(tB) + sb0[j], 0.0f);
        unsigned long long hA2 = pack2(hA, hA);
        unsigned long long hB2 = pack2(hB, hB);

        const ulonglong2* wr = (const ulonglong2*)(sW1t + j * HH1);
#pragma unroll
        for (int k2 = 0; k2 < HH1 / 4; k2++) {
            ulonglong2 wv = wr[k2];
            accA[2 * k2]     = fma2(hA2, wv.x, accA[2 * k2]);
            accA[2 * k2 + 1] = fma2(hA2, wv.y, accA[2 * k2 + 1]);
            accB[2 * k2]     = fma2(hB2, wv.x, accB[2 * k2]);
            accB[2 * k2 + 1] = fma2(hB2, wv.y, accB[2 * k2 + 1]);
        }
    }

    float predA = sbp, predB = sbp;
#pragma unroll
    for (int k = 0; k < HH1 / 2; k++) {
        float xA, yA, xB, yB;
        asm("mov.b64 {%0, %1}, %2;" : "=f"(xA), "=f"(yA) : "l"(accA[k]));
        asm("mov.b64 {%0, %1}, %2;" : "=f"(xB), "=f"(yB) : "l"(accB[k]));
        predA += fmaxf(xA, 0.0f) * sWp[2 * k] + fmaxf(yA, 0.0f) * sWp[2 * k + 1];
        predB += fmaxf(xB, 0.0f) * sWp[2 * k] + fmaxf(yB, 0.0f) * sWp[2 * k + 1];
    }
    out[e0] = predA;
    if (v1) out[e1] = predB;
}

// ---------------------------------------------------------------------------
// Launch: period-3 sequence (cosA, cosB, mlp). From R7-R11 sampling evidence
// the ncu window lands on global launch index 7 (0-based), and 7 mod 3 == 1
// -> cosB finally gets profiled. cos structure itself is the proven R7 one.
// Input order (metadata): edge_list, z1_trains, z2_trains(unused),
// weight_vec1, weight_vec2(unused), W0, b0, W1, b1, Wp, bp
// ---------------------------------------------------------------------------
extern "C" void kernel_launch(void* const* d_in, const int* in_sizes, int n_in,
                              void* d_out, int out_size) {
    const void*  edge = d_in[0];
    const float* z1   = (const float*)d_in[1];
    const float* w1   = (const float*)d_in[3];
    const float* W0   = (const float*)d_in[5];
    const float* b0   = (const float*)d_in[6];
    const float* W1   = (const float*)d_in[7];
    const float* b1   = (const float*)d_in[8];
    const float* Wp   = (const float*)d_in[9];
    const float* bp   = (const float*)d_in[10];

    const int HALF = TOTAL_ITEMS / 2;   // 100000: tp in {0,1} | {2,3}
    cos_kernel<<<888, CWARPS * 32>>>(edge, z1, w1, 0,    HALF);
    cos_kernel<<<888, CWARPS * 32>>>(edge, z1, w1, HALF, TOTAL_ITEMS);
    mlp_kernel<<<MLP_BLOCKS, 256>>>(W0, b0, W1, b1, Wp, bp, (float*)d_out);
}

// round 14
// speedup vs baseline: 1.2649x; 1.1295x over previous
#include <cuda_runtime.h>
#include <cstdint>

// Problem constants
#define TT   8
#define NN   100000
#define DD   128
#define EE   50000
#define HH0  64
#define HH1  32

// cos pipeline config (R7 shell): t-pair items, 4 rows (2KB) per stage
#define CWARPS 4          // warps per block
#define SLOTS  4          // smem slots per warp
#define PD     3          // prefetch distance (cp.async groups in flight)
#define STAGE_FLOATS 512  // 4 rows x 128 floats
#define STAGE_BYTES  2048
#define TOTAL_ITEMS  (4 * EE)    // 200k t-pair items: tp in 0..3

// mlp config: one wave, 2 edges per thread (kept unchanged)
#define MLP_BLOCKS 98
#define MLP_NT     (MLP_BLOCKS * 256)

__device__ float g_sim[EE * TT];   // s1 stored [e][t] for coalesced MLP reads

// Packed f32x2 helpers (Blackwell FFMA2 path — PTX only)
__device__ __forceinline__ unsigned long long mul2(unsigned long long a, unsigned long long b) {
    unsigned long long r;
    asm("mul.rn.f32x2 %0, %1, %2;" : "=l"(r) : "l"(a), "l"(b));
    return r;
}
__device__ __forceinline__ unsigned long long fma2(unsigned long long a, unsigned long long b, unsigned long long c) {
    unsigned long long r;
    asm("fma.rn.f32x2 %0, %1, %2, %3;" : "=l"(r) : "l"(a), "l"(b), "l"(c));
    return r;
}
__device__ __forceinline__ float hsum2(unsigned long long v) {
    float a, b;
    asm("mov.b64 {%0, %1}, %2;" : "=f"(a), "=f"(b) : "l"(v));
    return a + b;
}
__device__ __forceinline__ unsigned long long pack2(float lo, float hi) {
    unsigned long long r;
    asm("mov.b64 %0, {%1, %2};" : "=l"(r) : "f"(lo), "f"(hi));
    return r;
}

// 16B-chunk swizzle within a 512B row (q in 0..31): position = q ^ (q>>3).
__device__ __forceinline__ unsigned swz16(unsigned q) { return q ^ (q >> 3); }

// ---------------------------------------------------------------------------
// Cosine kernel — "quarter" layout (2x row replication, shared products).
// Item j -> tp = j/EE (0..3), e = j%EE; covers times (tp, tp+4), one edge
// fetch, 4 rows (2KB) per stage via cp.async (R7-proven pipeline shell).
//
// Lane roles:  q = lane>>3 (quarter), th = q>>1 (time half: tp / tp+4),
//              hp = q&1 (head pair {2hp, 2hp+1}), s = lane&7 (16-float chunk).
// Quarters {0,1} process time tp (heads {0,1} / {2,3}); quarters {2,3}
// process tp+4. Each 512B row is read by exactly 2 quarters (2x replication,
// vs 4x in R7) and each lane computes BOTH heads of its pair from shared
// products -> LDS.128/item 16->8, FMA2 96->72, SHFL 22->14.
// Reduction (8 lanes/quarter): xor1 on 6 sums, parity-select to 3, xor2,
// xor4, per-lane cosine (even lanes head A, odd head B), xor1 (pair sum),
// xor8 (combine quarter pairs; both time halves merge simultaneously).
// Lane 0 writes tp, lane 16 writes tp+4.
// ---------------------------------------------------------------------------
__global__ void __launch_bounds__(CWARPS * 32) cos_kernel(const void* __restrict__ el,
                                                          const float* __restrict__ z1,
                                                          const float* __restrict__ w1,
                                                          int jbeg, int jend) {
    __shared__ float sbuf[CWARPS][SLOTS][STAGE_FLOATS];

    const int lane = threadIdx.x & 31;
    const int wid  = threadIdx.x >> 5;
    const int q    = lane >> 3;      // quarter 0..3
    const int th   = q >> 1;         // time half 0/1
    const int hp   = q & 1;          // head pair
    const int s    = lane & 7;       // 16-float chunk 0..7
    const int gw   = (int)((blockIdx.x * blockDim.x + threadIdx.x) >> 5);
    const int nw   = (int)((gridDim.x * blockDim.x) >> 5);

    // Inline int64-vs-int32 edge dtype detection (warp-uniform)
    const int* ew = (const int*)el;
    int is64 = 1;
#pragma unroll
    for (int i = 1; i < 16; i += 2) is64 &= (ew[i] == 0);

    // Hoist w^2 for this lane's two heads on its 16-float chunk: 8 packed each
    unsigned long long w2a[8], w2b[8];
    {
        const ulonglong2* wp0 = (const ulonglong2*)(w1 + (2 * hp)     * DD + s * 16);
        const ulonglong2* wp1 = (const ulonglong2*)(w1 + (2 * hp + 1) * DD + s * 16);
#pragma unroll
        for (int i = 0; i < 4; i++) {
            ulonglong2 wv0 = __ldg(wp0 + i);
            ulonglong2 wv1 = __ldg(wp1 + i);
            w2a[2 * i]     = mul2(wv0.x, wv0.x);
            w2a[2 * i + 1] = mul2(wv0.y, wv0.y);
            w2b[2 * i]     = mul2(wv1.x, wv1.x);
            w2b[2 * i + 1] = mul2(wv1.y, wv1.y);
        }
    }

    // Read offsets: global 16B chunk (4s+c) lives at smem position swz16(.)
    unsigned roff[4];
#pragma unroll
    for (int c = 0; c < 4; c++) roff[c] = swz16((unsigned)(4 * s + c)) * 16;

    // cp.async: lane copies GLOBAL chunk `lane` into smem position swz16(lane)
    const unsigned goff = (unsigned)lane * 16;
    const unsigned woff = swz16((unsigned)lane) * 16;

    const unsigned sbase = (unsigned)__cvta_generic_to_shared(&sbuf[wid][0][0]);
    const unsigned toff  = (unsigned)th * 1024;   // this quarter's time rows

    // --- helpers -----------------------------------------------------------
    auto loadEdge = [&](int j) -> int2 {
        int jc = j < jend ? j : jend - 1;
        int e  = jc % EE;
        int2 r;
        if (is64) {
            longlong2 v = __ldg((const longlong2*)el + e);
            r.x = (int)v.x; r.y = (int)v.y;
        } else {
            r = __ldg((const int2*)el + e);
        }
        return r;
    };

    auto prefetch = [&](int j, int2 ed, int slot) {
        if (j < jend) {
            int tp = j / EE;
            const char* zA = (const char*)z1 + (size_t)tp * NN * 512;
            const char* zB = zA + (size_t)4 * NN * 512;
            const char* g0 = zA + (size_t)(unsigned)ed.x * 512 + goff;
            const char* g1 = zA + (size_t)(unsigned)ed.y * 512 + goff;
            const char* g2 = zB + (size_t)(unsigned)ed.x * 512 + goff;
            const char* g3 = zB + (size_t)(unsigned)ed.y * 512 + goff;
            unsigned sm = sbase + (unsigned)slot * STAGE_BYTES + woff;
            asm volatile("cp.async.cg.shared.global [%0], [%1], 16;\n" :: "r"(sm),        "l"(g0));
            asm volatile("cp.async.cg.shared.global [%0], [%1], 16;\n" :: "r"(sm + 512),  "l"(g1));
            asm volatile("cp.async.cg.shared.global [%0], [%1], 16;\n" :: "r"(sm + 1024), "l"(g2));
            asm volatile("cp.async.cg.shared.global [%0], [%1], 16;\n" :: "r"(sm + 1536), "l"(g3));
        }
        asm volatile("cp.async.commit_group;\n");  // empty group OK when guarded out
    };
    // ------------------------------------------------------------------------

    const int j0 = jbeg + gw;
    // Prologue: PD groups in flight + edge register ring 2 iterations deep
    prefetch(j0,          loadEdge(j0),          0);
    prefetch(j0 + nw,     loadEdge(j0 + nw),     1);
    prefetch(j0 + 2 * nw, loadEdge(j0 + 2 * nw), 2);
    int2 ering[2];
    ering[0] = loadEdge(j0 + 3 * nw);
    ering[1] = loadEdge(j0 + 4 * nw);

    int cnt = 0;
#pragma unroll 1
    for (int j = j0; j < jend; j += nw, cnt++) {
        asm volatile("cp.async.wait_group %0;\n" :: "n"(PD - 1));
        __syncwarp();

        const int slot = cnt & (SLOTS - 1);
        const char* st = (const char*)&sbuf[wid][slot][0] + toff;

        // ---- compute: both heads of this quarter's pair, its time half ----
        unsigned long long dA = 0ull, nA = 0ull, mA = 0ull;
        unsigned long long dB = 0ull, nB = 0ull, mB = 0ull;
#pragma unroll
        for (int c = 0; c < 4; c++) {
            ulonglong2 a = *(const ulonglong2*)(st +       roff[c]);
            ulonglong2 b = *(const ulonglong2*)(st + 512 + roff[c]);

            unsigned long long pab = mul2(a.x, b.x);
            unsigned long long paa = mul2(a.x, a.x);
            unsigned long long pbb = mul2(b.x, b.x);
            dA = fma2(pab, w2a[2 * c], dA);
            nA = fma2(paa, w2a[2 * c], nA);
            mA = fma2(pbb, w2a[2 * c], mA);
            dB = fma2(pab, w2b[2 * c], dB);
            nB = fma2(paa, w2b[2 * c], nB);
            mB = fma2(pbb, w2b[2 * c], mB);

            pab = mul2(a.y, b.y);
            paa = mul2(a.y, a.y);
            pbb = mul2(b.y, b.y);
            dA = fma2(pab, w2a[2 * c + 1], dA);
            nA = fma2(paa, w2a[2 * c + 1], nA);
            mA = fma2(pbb, w2a[2 * c + 1], mA);
            dB = fma2(pab, w2b[2 * c + 1], dB);
            nB = fma2(paa, w2b[2 * c + 1], nB);
            mB = fma2(pbb, w2b[2 * c + 1], mB);
        }

        // Prefetch next stage NOW so LDGSTS issue overlaps the reduction tail
        prefetch(j + PD * nw, ering[cnt & 1], (cnt + PD) & (SLOTS - 1));
        ering[cnt & 1] = loadEdge(j + 5 * nw);

        float d0 = hsum2(dA), n0 = hsum2(nA), m0 = hsum2(mA);
        float d1 = hsum2(dB), n1 = hsum2(nB), m1 = hsum2(mB);

        // xor1 on all six partial sums (pairs of lanes now identical)
        d0 += __shfl_xor_sync(0xffffffffu, d0, 1);
        d1 += __shfl_xor_sync(0xffffffffu, d1, 1);
        n0 += __shfl_xor_sync(0xffffffffu, n0, 1);
        n1 += __shfl_xor_sync(0xffffffffu, n1, 1);
        m0 += __shfl_xor_sync(0xffffffffu, m0, 1);
        m1 += __shfl_xor_sync(0xffffffffu, m1, 1);

        // Parity split: even lanes carry head A, odd lanes head B
        const bool oddl = (lane & 1);
        float d = oddl ? d1 : d0;
        float n = oddl ? n1 : n0;
        float m = oddl ? m1 : m0;

        // Finish the 8-lane reduction on 3 values (parity-preserving xors)
        d += __shfl_xor_sync(0xffffffffu, d, 2);
        n += __shfl_xor_sync(0xffffffffu, n, 2);
        m += __shfl_xor_sync(0xffffffffu, m, 2);
        d += __shfl_xor_sync(0xffffffffu, d, 4);
        n += __shfl_xor_sync(0xffffffffu, n, 4);
        m += __shfl_xor_sync(0xffffffffu, m, 4);

        // max(sqrt(x), 1e-8) == sqrt(max(x, 1e-16)) for x >= 0
        float c = d * rsqrtf(fmaxf(n, 1e-16f) * fmaxf(m, 1e-16f));

        // Head-pair sum, then combine the two quarters of each time half
        c += __shfl_xor_sync(0xffffffffu, c, 1);
        c += __shfl_xor_sync(0xffffffffu, c, 8);

        const int tp = j / EE;
        const int e  = j - tp * EE;
        if (lane == 0)  g_sim[e * TT + tp]     = 0.25f * c;
        if (lane == 16) g_sim[e * TT + tp + 4] = 0.25f * c;
    }
}

// ---------------------------------------------------------------------------
// MLP kernel (kept unchanged): TWO edges per thread, one wave (98 blocks).
// ---------------------------------------------------------------------------
__global__ void __launch_bounds__(256) mlp_kernel(const float* __restrict__ W0,
                                                  const float* __restrict__ b0,
                                                  const float* __restrict__ W1,
                                                  const float* __restrict__ b1,
                                                  const float* __restrict__ Wp,
                                                  const float* __restrict__ bp,
                                                  float* __restrict__ out) {
    __shared__ float sW0[HH0 * TT];        // 512
    __shared__ float sb0[HH0];
    __shared__ float sW1t[HH0 * HH1];      // transposed: [j][k]
    __shared__ float sb1[HH1];
    __shared__ float sWp[HH1];
    __shared__ float sbp;

    const int tid = threadIdx.x;
    for (int i = tid; i < HH0 * TT; i += 256) sW0[i] = W0[i];
    for (int i = tid; i < HH1 * HH0; i += 256) {
        int k = i / HH0, j = i - k * HH0;          // W1 is [k][j]
        sW1t[j * HH1 + k] = W1[i];
    }
    if (tid < HH0) sb0[tid] = b0[tid];
    if (tid < HH1) { sb1[tid] = b1[tid]; sWp[tid] = Wp[tid]; }
    if (tid == 0) sbp = bp[0];
    __syncthreads();

    const int e0 = blockIdx.x * 256 + tid;
    const int e1 = e0 + MLP_NT;
    const bool v1 = (e1 < EE);
    const int e1c = v1 ? e1 : (EE - 1);

    ulonglong2 sva0 = *(const ulonglong2*)(g_sim + e0  * 8);
    ulonglong2 sva1 = *(const ulonglong2*)(g_sim + e0  * 8 + 4);
    ulonglong2 svb0 = *(const ulonglong2*)(g_sim + e1c * 8);
    ulonglong2 svb1 = *(const ulonglong2*)(g_sim + e1c * 8 + 4);

    unsigned long long accA[HH1 / 2], accB[HH1 / 2];
#pragma unroll
    for (int k = 0; k < HH1 / 2; k++) {
        unsigned long long b = ((const unsigned long long*)sb1)[k];
        accA[k] = b; accB[k] = b;
    }

#pragma unroll
    for (int j = 0; j < HH0; j++) {
        const ulonglong2* w = (const ulonglong2*)(sW0 + j * TT);
        ulonglong2 w0 = w[0], w1v = w[1];

        unsigned long long tA = mul2(sva0.x, w0.x);
        unsigned long long tB = mul2(svb0.x, w0.x);
        tA = fma2(sva0.y, w0.y, tA);
        tB = fma2(svb0.y, w0.y, tB);
        tA = fma2(sva1.x, w1v.x, tA);
        tB = fma2(svb1.x, w1v.x, tB);
        tA = fma2(sva1.y, w1v.y, tA);
        tB = fma2(svb1.y, w1v.y, tB);
        float hA = fmaxf(hsum2(tA) + sb0[j], 0.0f);
        float hB = fmaxf(hsum2(tB) + sb0[j], 0.0f);
        unsigned long long hA2 = pack2(hA, hA);
        unsigned long long hB2 = pack2(hB, hB);

        const ulonglong2* wr = (const ulonglong2*)(sW1t + j * HH1);
#pragma unroll
        for (int k2 = 0; k2 < HH1 / 4; k2++) {
            ulonglong2 wv = wr[k2];
            accA[2 * k2]     = fma2(hA2, wv.x, accA[2 * k2]);
            accA[2 * k2 + 1] = fma2(hA2, wv.y, accA[2 * k2 + 1]);
            accB[2 * k2]     = fma2(hB2, wv.x, accB[2 * k2]);
            accB[2 * k2 + 1] = fma2(hB2, wv.y, accB[2 * k2 + 1]);
        }
    }

    float predA = sbp, predB = sbp;
#pragma unroll
    for (int k = 0; k < HH1 / 2; k++) {
        float xA, yA, xB, yB;
        asm("mov.b64 {%0, %1}, %2;" : "=f"(xA), "=f"(yA) : "l"(accA[k]));
        asm("mov.b64 {%0, %1}, %2;" : "=f"(xB), "=f"(yB) : "l"(accB[k]));
        predA += fmaxf(xA, 0.0f) * sWp[2 * k] + fmaxf(yA, 0.0f) * sWp[2 * k + 1];
        predB += fmaxf(xB, 0.0f) * sWp[2 * k] + fmaxf(yB, 0.0f) * sWp[2 * k + 1];
    }
    out[e0] = predA;
    if (v1) out[e1] = predB;
}

// ---------------------------------------------------------------------------
// Launch: period-3 (cosA, cosB, mlp) keeps ncu's fixed window (launch index 7,
// 7 mod 3 == 1) on cosB. Input order (metadata): edge_list, z1_trains,
// z2_trains(unused), weight_vec1, weight_vec2(unused), W0, b0, W1, b1, Wp, bp
// ---------------------------------------------------------------------------
extern "C" void kernel_launch(void* const* d_in, const int* in_sizes, int n_in,
                              void* d_out, int out_size) {
    const void*  edge = d_in[0];
    const float* z1   = (const float*)d_in[1];
    const float* w1   = (const float*)d_in[3];
    const float* W0   = (const float*)d_in[5];
    const float* b0   = (const float*)d_in[6];
    const float* W1   = (const float*)d_in[7];
    const float* b1   = (const float*)d_in[8];
    const float* Wp   = (const float*)d_in[9];
    const float* bp   = (const float*)d_in[10];

    const int HALF = TOTAL_ITEMS / 2;   // tp in {0,1} | {2,3}
    cos_kernel<<<888, CWARPS * 32>>>(edge, z1, w1, 0,    HALF);
    cos_kernel<<<888, CWARPS * 32>>>(edge, z1, w1, HALF, TOTAL_ITEMS);
    mlp_kernel<<<MLP_BLOCKS, 256>>>(W0, b0, W1, b1, Wp, bp, (float*)d_out);
}

// round 15
// speedup vs baseline: 1.3040x; 1.0309x over previous
#include <cuda_runtime.h>
#include <cstdint>

// Problem constants
#define TT   8
#define NN   100000
#define DD   128
#define EE   50000
#define HH0  64
#define HH1  32

// cos pipeline config (R14 proven): t-pair items, 4 rows (2KB) per stage
#define CWARPS 4          // warps per block
#define SLOTS  4          // smem slots per warp
#define PD     3          // prefetch distance (cp.async groups in flight)
#define STAGE_FLOATS 512  // 4 rows x 128 floats
#define STAGE_BYTES  2048
#define TOTAL_ITEMS  (4 * EE)    // 200k t-pair items: tp in 0..3

// mlp config: one FULL wave (148 blocks = 1/SM), 2 strided edges per thread
#define MLP_BLOCKS 148
#define MLP_NT     (MLP_BLOCKS * 256)   // 37888

__device__ float g_sim[EE * TT];   // s1 stored [e][t] for coalesced MLP reads

// Packed f32x2 helpers (Blackwell FFMA2 path — PTX only)
__device__ __forceinline__ unsigned long long mul2(unsigned long long a, unsigned long long b) {
    unsigned long long r;
    asm("mul.rn.f32x2 %0, %1, %2;" : "=l"(r) : "l"(a), "l"(b));
    return r;
}
__device__ __forceinline__ unsigned long long fma2(unsigned long long a, unsigned long long b, unsigned long long c) {
    unsigned long long r;
    asm("fma.rn.f32x2 %0, %1, %2, %3;" : "=l"(r) : "l"(a), "l"(b), "l"(c));
    return r;
}
__device__ __forceinline__ float hsum2(unsigned long long v) {
    float a, b;
    asm("mov.b64 {%0, %1}, %2;" : "=f"(a), "=f"(b) : "l"(v));
    return a + b;
}
__device__ __forceinline__ unsigned long long pack2(float lo, float hi) {
    unsigned long long r;
    asm("mov.b64 %0, {%1, %2};" : "=l"(r) : "f"(lo), "f"(hi));
    return r;
}

// 16B-chunk swizzle within a 512B row (q in 0..31): position = q ^ (q>>3).
__device__ __forceinline__ unsigned swz16(unsigned q) { return q ^ (q >> 3); }

// ---------------------------------------------------------------------------
// Cosine kernel — R14 "quarter" layout (2x row replication, shared products),
// now as ONE launch over all 200k items (the two-half split was diagnostic;
// merging saves its fill/drain/tail cost).
// Item j -> tp = j/EE (0..3), e = j%EE; covers times (tp, tp+4), one edge
// fetch, 4 rows (2KB) per stage via cp.async.
// Lane roles:  q = lane>>3 (quarter), th = q>>1 (time half), hp = q&1
// (head pair {2hp,2hp+1}), s = lane&7 (16-float chunk).
// Each 512B row is read by exactly 2 quarters; each lane computes BOTH heads
// of its pair from shared products. 8 LDS.128 + 14 SHFL per item.
// ---------------------------------------------------------------------------
__global__ void __launch_bounds__(CWARPS * 32) cos_kernel(const void* __restrict__ el,
                                                          const float* __restrict__ z1,
                                                          const float* __restrict__ w1) {
    __shared__ float sbuf[CWARPS][SLOTS][STAGE_FLOATS];

    const int lane = threadIdx.x & 31;
    const int wid  = threadIdx.x >> 5;
    const int q    = lane >> 3;      // quarter 0..3
    const int th   = q >> 1;         // time half 0/1
    const int hp   = q & 1;          // head pair
    const int s    = lane & 7;       // 16-float chunk 0..7
    const int gw   = (int)((blockIdx.x * blockDim.x + threadIdx.x) >> 5);
    const int nw   = (int)((gridDim.x * blockDim.x) >> 5);
    const int jend = TOTAL_ITEMS;

    // Inline int64-vs-int32 edge dtype detection (warp-uniform)
    const int* ew = (const int*)el;
    int is64 = 1;
#pragma unroll
    for (int i = 1; i < 16; i += 2) is64 &= (ew[i] == 0);

    // Hoist w^2 for this lane's two heads on its 16-float chunk: 8 packed each
    unsigned long long w2a[8], w2b[8];
    {
        const ulonglong2* wp0 = (const ulonglong2*)(w1 + (2 * hp)     * DD + s * 16);
        const ulonglong2* wp1 = (const ulonglong2*)(w1 + (2 * hp + 1) * DD + s * 16);
#pragma unroll
        for (int i = 0; i < 4; i++) {
            ulonglong2 wv0 = __ldg(wp0 + i);
            ulonglong2 wv1 = __ldg(wp1 + i);
            w2a[2 * i]     = mul2(wv0.x, wv0.x);
            w2a[2 * i + 1] = mul2(wv0.y, wv0.y);
            w2b[2 * i]     = mul2(wv1.x, wv1.x);
            w2b[2 * i + 1] = mul2(wv1.y, wv1.y);
        }
    }

    // Read offsets: global 16B chunk (4s+c) lives at smem position swz16(.)
    unsigned roff[4];
#pragma unroll
    for (int c = 0; c < 4; c++) roff[c] = swz16((unsigned)(4 * s + c)) * 16;

    // cp.async: lane copies GLOBAL chunk `lane` into smem position swz16(lane)
    const unsigned goff = (unsigned)lane * 16;
    const unsigned woff = swz16((unsigned)lane) * 16;

    const unsigned sbase = (unsigned)__cvta_generic_to_shared(&sbuf[wid][0][0]);
    const unsigned toff  = (unsigned)th * 1024;   // this quarter's time rows

    // --- helpers -----------------------------------------------------------
    auto loadEdge = [&](int j) -> int2 {
        int jc = j < jend ? j : jend - 1;
        int e  = jc % EE;
        int2 r;
        if (is64) {
            longlong2 v = __ldg((const longlong2*)el + e);
            r.x = (int)v.x; r.y = (int)v.y;
        } else {
            r = __ldg((const int2*)el + e);
        }
        return r;
    };

    auto prefetch = [&](int j, int2 ed, int slot) {
        if (j < jend) {
            int tp = j / EE;
            const char* zA = (const char*)z1 + (size_t)tp * NN * 512;
            const char* zB = zA + (size_t)4 * NN * 512;
            const char* g0 = zA + (size_t)(unsigned)ed.x * 512 + goff;
            const char* g1 = zA + (size_t)(unsigned)ed.y * 512 + goff;
            const char* g2 = zB + (size_t)(unsigned)ed.x * 512 + goff;
            const char* g3 = zB + (size_t)(unsigned)ed.y * 512 + goff;
            unsigned sm = sbase + (unsigned)slot * STAGE_BYTES + woff;
            asm volatile("cp.async.cg.shared.global [%0], [%1], 16;\n" :: "r"(sm),        "l"(g0));
            asm volatile("cp.async.cg.shared.global [%0], [%1], 16;\n" :: "r"(sm + 512),  "l"(g1));
            asm volatile("cp.async.cg.shared.global [%0], [%1], 16;\n" :: "r"(sm + 1024), "l"(g2));
            asm volatile("cp.async.cg.shared.global [%0], [%1], 16;\n" :: "r"(sm + 1536), "l"(g3));
        }
        asm volatile("cp.async.commit_group;\n");  // empty group OK when guarded out
    };
    // ------------------------------------------------------------------------

    const int j0 = gw;
    // Prologue: PD groups in flight + edge register ring 2 iterations deep
    prefetch(j0,          loadEdge(j0),          0);
    prefetch(j0 + nw,     loadEdge(j0 + nw),     1);
    prefetch(j0 + 2 * nw, loadEdge(j0 + 2 * nw), 2);
    int2 ering[2];
    ering[0] = loadEdge(j0 + 3 * nw);
    ering[1] = loadEdge(j0 + 4 * nw);

    int cnt = 0;
#pragma unroll 1
    for (int j = j0; j < jend; j += nw, cnt++) {
        asm volatile("cp.async.wait_group %0;\n" :: "n"(PD - 1));
        __syncwarp();

        const int slot = cnt & (SLOTS - 1);
        const char* st = (const char*)&sbuf[wid][slot][0] + toff;

        // ---- compute: both heads of this quarter's pair, its time half ----
        unsigned long long dA = 0ull, nA = 0ull, mA = 0ull;
        unsigned long long dB = 0ull, nB = 0ull, mB = 0ull;
#pragma unroll
        for (int c = 0; c < 4; c++) {
            ulonglong2 a = *(const ulonglong2*)(st +       roff[c]);
            ulonglong2 b = *(const ulonglong2*)(st + 512 + roff[c]);

            unsigned long long pab = mul2(a.x, b.x);
            unsigned long long paa = mul2(a.x, a.x);
            unsigned long long pbb = mul2(b.x, b.x);
            dA = fma2(pab, w2a[2 * c], dA);
            nA = fma2(paa, w2a[2 * c], nA);
            mA = fma2(pbb, w2a[2 * c], mA);
            dB = fma2(pab, w2b[2 * c], dB);
            nB = fma2(paa, w2b[2 * c], nB);
            mB = fma2(pbb, w2b[2 * c], mB);

            pab = mul2(a.y, b.y);
            paa = mul2(a.y, a.y);
            pbb = mul2(b.y, b.y);
            dA = fma2(pab, w2a[2 * c + 1], dA);
            nA = fma2(paa, w2a[2 * c + 1], nA);
            mA = fma2(pbb, w2a[2 * c + 1], mA);
            dB = fma2(pab, w2b[2 * c + 1], dB);
            nB = fma2(paa, w2b[2 * c + 1], nB);
            mB = fma2(pbb, w2b[2 * c + 1], mB);
        }

        // Prefetch next stage NOW so LDGSTS issue overlaps the reduction tail
        prefetch(j + PD * nw, ering[cnt & 1], (cnt + PD) & (SLOTS - 1));
        ering[cnt & 1] = loadEdge(j + 5 * nw);

        float d0 = hsum2(dA), n0 = hsum2(nA), m0 = hsum2(mA);
        float d1 = hsum2(dB), n1 = hsum2(nB), m1 = hsum2(mB);

        // xor1 on all six partial sums (pairs of lanes now identical)
        d0 += __shfl_xor_sync(0xffffffffu, d0, 1);
        d1 += __shfl_xor_sync(0xffffffffu, d1, 1);
        n0 += __shfl_xor_sync(0xffffffffu, n0, 1);
        n1 += __shfl_xor_sync(0xffffffffu, n1, 1);
        m0 += __shfl_xor_sync(0xffffffffu, m0, 1);
        m1 += __shfl_xor_sync(0xffffffffu, m1, 1);

        // Parity split: even lanes carry head A, odd lanes head B
        const bool oddl = (lane & 1);
        float d = oddl ? d1 : d0;
        float n = oddl ? n1 : n0;
        float m = oddl ? m1 : m0;

        // Finish the 8-lane reduction on 3 values (parity-preserving xors)
        d += __shfl_xor_sync(0xffffffffu, d, 2);
        n += __shfl_xor_sync(0xffffffffu, n, 2);
        m += __shfl_xor_sync(0xffffffffu, m, 2);
        d += __shfl_xor_sync(0xffffffffu, d, 4);
        n += __shfl_xor_sync(0xffffffffu, n, 4);
        m += __shfl_xor_sync(0xffffffffu, m, 4);

        // max(sqrt(x), 1e-8) == sqrt(max(x, 1e-16)) for x >= 0
        float c = d * rsqrtf(fmaxf(n, 1e-16f) * fmaxf(m, 1e-16f));

        // Head-pair sum, then combine the two quarters of each time half
        c += __shfl_xor_sync(0xffffffffu, c, 1);
        c += __shfl_xor_sync(0xffffffffu, c, 8);

        const int tp = j / EE;
        const int e  = j - tp * EE;
        if (lane == 0)  g_sim[e * TT + tp]     = 0.25f * c;
        if (lane == 16) g_sim[e * TT + tp + 4] = 0.25f * c;
    }
}

// ---------------------------------------------------------------------------
// MLP kernel: 148 blocks (exactly one per SM — the 98-block version left 50
// SMs idle, occ 12%). Thread gid owns e0 = gid and e1 = gid + 37888 (only
// 12112 threads have a valid e1). Warp-uniform sW0/sW1t rows preserved.
// ---------------------------------------------------------------------------
__global__ void __launch_bounds__(256) mlp_kernel(const float* __restrict__ W0,
                                                  const float* __restrict__ b0,
                                                  const float* __restrict__ W1,
                                                  const float* __restrict__ b1,
                                                  const float* __restrict__ Wp,
                                                  const float* __restrict__ bp,
                                                  float* __restrict__ out) {
    __shared__ float sW0[HH0 * TT];        // 512
    __shared__ float sb0[HH0];
    __shared__ float sW1t[HH0 * HH1];      // transposed: [j][k]
    __shared__ float sb1[HH1];
    __shared__ float sWp[HH1];
    __shared__ float sbp;

    const int tid = threadIdx.x;
    for (int i = tid; i < HH0 * TT; i += 256) sW0[i] = W0[i];
    for (int i = tid; i < HH1 * HH0; i += 256) {
        int k = i / HH0, j = i - k * HH0;          // W1 is [k][j]
        sW1t[j * HH1 + k] = W1[i];
    }
    if (tid < HH0) sb0[tid] = b0[tid];
    if (tid < HH1) { sb1[tid] = b1[tid]; sWp[tid] = Wp[tid]; }
    if (tid == 0) sbp = bp[0];
    __syncthreads();

    const int e0 = blockIdx.x * 256 + tid;       // < 37888 < EE always
    const int e1 = e0 + MLP_NT;
    const bool v1 = (e1 < EE);
    const int e1c = v1 ? e1 : (EE - 1);

    ulonglong2 sva0 = *(const ulonglong2*)(g_sim + e0  * 8);
    ulonglong2 sva1 = *(const ulonglong2*)(g_sim + e0  * 8 + 4);
    ulonglong2 svb0 = *(const ulonglong2*)(g_sim + e1c * 8);
    ulonglong2 svb1 = *(const ulonglong2*)(g_sim + e1c * 8 + 4);

    unsigned long long accA[HH1 / 2], accB[HH1 / 2];
#pragma unroll
    for (int k = 0; k < HH1 / 2; k++) {
        unsigned long long b = ((const unsigned long long*)sb1)[k];
        accA[k] = b; accB[k] = b;
    }

#pragma unroll
    for (int j = 0; j < HH0; j++) {
        const ulonglong2* w = (const ulonglong2*)(sW0 + j * TT);
        ulonglong2 w0 = w[0], w1v = w[1];

        unsigned long long tA = mul2(sva0.x, w0.x);
        unsigned long long tB = mul2(svb0.x, w0.x);
        tA = fma2(sva0.y, w0.y, tA);
        tB = fma2(svb0.y, w0.y, tB);
        tA = fma2(sva1.x, w1v.x, tA);
        tB = fma2(svb1.x, w1v.x, tB);
        tA = fma2(sva1.y, w1v.y, tA);
        tB = fma2(svb1.y, w1v.y, tB);
        float hA = fmaxf(hsum2(tA) + sb0[j], 0.0f);
        float hB = fmaxf(hsum2(tB) + sb0[j], 0.0f);
        unsigned long long hA2 = pack2(hA, hA);
        unsigned long long hB2 = pack2(hB, hB);

        const ulonglong2* wr = (const ulonglong2*)(sW1t + j * HH1);
#pragma unroll
        for (int k2 = 0; k2 < HH1 / 4; k2++) {
            ulonglong2 wv = wr[k2];
            accA[2 * k2]     = fma2(hA2, wv.x, accA[2 * k2]);
            accA[2 * k2 + 1] = fma2(hA2, wv.y, accA[2 * k2 + 1]);
            accB[2 * k2]     = fma2(hB2, wv.x, accB[2 * k2]);
            accB[2 * k2 + 1] = fma2(hB2, wv.y, accB[2 * k2 + 1]);
        }
    }

    float predA = sbp, predB = sbp;
#pragma unroll
    for (int k = 0; k < HH1 / 2; k++) {
        float xA, yA, xB, yB;
        asm("mov.b64 {%0, %1}, %2;" : "=f"(xA), "=f"(yA) : "l"(accA[k]));
        asm("mov.b64 {%0, %1}, %2;" : "=f"(xB), "=f"(yB) : "l"(accB[k]));
        predA += fmaxf(xA, 0.0f) * sWp[2 * k] + fmaxf(yA, 0.0f) * sWp[2 * k + 1];
        predB += fmaxf(xB, 0.0f) * sWp[2 * k] + fmaxf(yB, 0.0f) * sWp[2 * k + 1];
    }
    out[e0] = predA;
    if (v1) out[e1] = predB;
}

// ---------------------------------------------------------------------------
// Launch: single cos launch (split served its diagnostic purpose) + mlp.
// Input order (metadata): edge_list, z1_trains, z2_trains(unused),
// weight_vec1, weight_vec2(unused), W0, b0, W1, b1, Wp, bp
// ---------------------------------------------------------------------------
extern "C" void kernel_launch(void* const* d_in, const int* in_sizes, int n_in,
                              void* d_out, int out_size) {
    const void*  edge = d_in[0];
    const float* z1   = (const float*)d_in[1];
    const float* w1   = (const float*)d_in[3];
    const float* W0   = (const float*)d_in[5];
    const float* b0   = (const float*)d_in[6];
    const float* W1   = (const float*)d_in[7];
    const float* b1   = (const float*)d_in[8];
    const float* Wp   = (const float*)d_in[9];
    const float* bp   = (const float*)d_in[10];

    cos_kernel<<<888, CWARPS * 32>>>(edge, z1, w1);
    mlp_kernel<<<MLP_BLOCKS, 256>>>(W0, b0, W1, b1, Wp, bp, (float*)d_out);
}